// round 1
// baseline (speedup 1.0000x reference)
#include <cuda_runtime.h>
#include <math.h>

#define NB 32768
#define NT (NB*4)          // 131072 tokens
#define DD 256
#define NH 8
#define DHD 32
#define QK_SCALE 0.17677669529663687f   // 1/sqrt(32)

typedef unsigned long long u64;

// Scratch (static device globals — sanctioned workaround, no runtime alloc)
__device__ float g_P[(size_t)NT * 1024];   // per-token [Q|K|V|R], 536 MB
__device__ float g_att[(size_t)NT * DD];   // attention output before Wo, 134 MB

// ---------------- f32x2 helpers (FFMA2 path: 2x fp32 FMA throughput) -------
__device__ __forceinline__ u64 pack2(float x, float y) {
    u64 r; asm("mov.b64 %0, {%1, %2};" : "=l"(r) : "f"(x), "f"(y)); return r;
}
__device__ __forceinline__ void unpack2(u64 v, float &x, float &y) {
    asm("mov.b64 {%0, %1}, %2;" : "=f"(x), "=f"(y) : "l"(v));
}
__device__ __forceinline__ u64 ffma2(u64 a, u64 b, u64 c) {
    u64 d; asm("fma.rn.f32x2 %0, %1, %2, %3;" : "=l"(d) : "l"(a), "l"(b), "l"(c));
    return d;
}

// ============================================================================
// K1: P[t, 0:1024] = tokens[t,:] @ [Wq|Wk|Wv|Wr]^T
// M=131072, N=1024 (4 weight slabs of 256), K=256.
// BM=128, BN=128, BK=16; 256 threads; 8x8 micro-tile via f32x2 token-pairs.
// grid = (1024, 8): by selects weight (by>>1) and 128-col half (by&1).
// ============================================================================
__global__ __launch_bounds__(256)
void k_gemm_qkvr(const float* __restrict__ X,
                 const float* __restrict__ Wq, const float* __restrict__ Wk,
                 const float* __restrict__ Wv, const float* __restrict__ Wr)
{
    __shared__ __align__(16) float As[16 * 128];  // [k][token]
    __shared__ __align__(16) float Bs[16 * 128];  // [k][out]

    const int tid = threadIdx.x;
    const int bx = blockIdx.x, by = blockIdx.y;
    const float* W = (by < 2) ? Wq : (by < 4) ? Wk : (by < 6) ? Wv : Wr;
    const int jbase_w = (by & 1) * 128;           // row offset inside the 256x256 weight
    const long row0 = (long)bx * 128;

    const int ty = tid >> 4;   // 16 token-groups of 8
    const int tx = tid & 15;   // 16 out-groups of 8

    u64 acc[4][8];
#pragma unroll
    for (int i = 0; i < 4; i++)
#pragma unroll
        for (int u = 0; u < 8; u++) acc[i][u] = 0ULL;  // {+0.f,+0.f}

    for (int k0 = 0; k0 < 256; k0 += 16) {
        // Load A tile 128x16 (2 float4/thread), store transposed [k][t]
#pragma unroll
        for (int s = 0; s < 2; s++) {
            int i = tid + s * 256;
            int r = i >> 2, c4 = i & 3;
            float4 v = *(const float4*)&X[(row0 + r) * 256 + k0 + c4 * 4];
            As[(c4 * 4 + 0) * 128 + r] = v.x;
            As[(c4 * 4 + 1) * 128 + r] = v.y;
            As[(c4 * 4 + 2) * 128 + r] = v.z;
            As[(c4 * 4 + 3) * 128 + r] = v.w;
        }
        // Load B tile 128x16 (W rows jbase_w..+128), store transposed [k][j]
#pragma unroll
        for (int s = 0; s < 2; s++) {
            int i = tid + s * 256;
            int r = i >> 2, c4 = i & 3;
            float4 v = *(const float4*)&W[(jbase_w + r) * 256 + k0 + c4 * 4];
            Bs[(c4 * 4 + 0) * 128 + r] = v.x;
            Bs[(c4 * 4 + 1) * 128 + r] = v.y;
            Bs[(c4 * 4 + 2) * 128 + r] = v.z;
            Bs[(c4 * 4 + 3) * 128 + r] = v.w;
        }
        __syncthreads();

#pragma unroll
        for (int kk = 0; kk < 16; kk++) {
            u64 a[4];
#pragma unroll
            for (int i = 0; i < 4; i++)
                a[i] = *(const u64*)&As[kk * 128 + ty * 8 + i * 2];
            float4 b0 = *(const float4*)&Bs[kk * 128 + tx * 8];
            float4 b1 = *(const float4*)&Bs[kk * 128 + tx * 8 + 4];
            u64 bb[8];
            bb[0] = pack2(b0.x, b0.x); bb[1] = pack2(b0.y, b0.y);
            bb[2] = pack2(b0.z, b0.z); bb[3] = pack2(b0.w, b0.w);
            bb[4] = pack2(b1.x, b1.x); bb[5] = pack2(b1.y, b1.y);
            bb[6] = pack2(b1.z, b1.z); bb[7] = pack2(b1.w, b1.w);
#pragma unroll
            for (int i = 0; i < 4; i++)
#pragma unroll
                for (int u = 0; u < 8; u++)
                    acc[i][u] = ffma2(a[i], bb[u], acc[i][u]);
        }
        __syncthreads();
    }

    // Epilogue: write P
    const long colbase = (long)by * 128 + tx * 8;
#pragma unroll
    for (int i = 0; i < 4; i++) {
        float lo[8], hi[8];
#pragma unroll
        for (int u = 0; u < 8; u++) unpack2(acc[i][u], lo[u], hi[u]);
        long t0 = row0 + ty * 8 + i * 2;
        float4* p0 = (float4*)&g_P[t0 * 1024 + colbase];
        p0[0] = make_float4(lo[0], lo[1], lo[2], lo[3]);
        p0[1] = make_float4(lo[4], lo[5], lo[6], lo[7]);
        float4* p1 = (float4*)&g_P[(t0 + 1) * 1024 + colbase];
        p1[0] = make_float4(hi[0], hi[1], hi[2], hi[3]);
        p1[1] = make_float4(hi[4], hi[5], hi[6], hi[7]);
    }
}

// ============================================================================
// K2: per-sample 3-neighbor attention. One warp per sample; lane = (i, h).
// Reads g_P, writes g_att (pre-Wo attention output) and attn probabilities.
// ============================================================================
__global__ __launch_bounds__(128)
void k_attn(float* __restrict__ attn_out)
{
    const int b = blockIdx.x * 4 + (threadIdx.x >> 5);
    const int lane = threadIdx.x & 31;
    const int i = lane >> 3;     // token in sample (0..3)
    const int h = lane & 7;      // head (0..7)
    const long t = (long)b * 4 + i;

    // Load Q head vector (32 floats)
    float Q[32];
    const float* qp = &g_P[t * 1024 + h * 32];
#pragma unroll
    for (int d4 = 0; d4 < 8; d4++) {
        float4 v = *(const float4*)&qp[d4 * 4];
        Q[d4 * 4 + 0] = v.x; Q[d4 * 4 + 1] = v.y;
        Q[d4 * 4 + 2] = v.z; Q[d4 * 4 + 3] = v.w;
    }

    // Scores over 3 neighbors
    float s[3];
#pragma unroll
    for (int l = 0; l < 3; l++) {
        int nb = (l >= i) ? l + 1 : l;             // NEIGH[i][l]
        const float* kp = &g_P[((long)b * 4 + nb) * 1024 + 256 + h * 32];
        float acc = 0.f;
#pragma unroll
        for (int d4 = 0; d4 < 8; d4++) {
            float4 v = *(const float4*)&kp[d4 * 4];
            acc = fmaf(Q[d4 * 4 + 0], v.x, acc);
            acc = fmaf(Q[d4 * 4 + 1], v.y, acc);
            acc = fmaf(Q[d4 * 4 + 2], v.z, acc);
            acc = fmaf(Q[d4 * 4 + 3], v.w, acc);
        }
        s[l] = acc * QK_SCALE;
    }

    // Softmax over 3
    float m = fmaxf(s[0], fmaxf(s[1], s[2]));
    float e0 = expf(s[0] - m), e1 = expf(s[1] - m), e2 = expf(s[2] - m);
    float inv = 1.f / (e0 + e1 + e2);
    float a[3] = { e0 * inv, e1 * inv, e2 * inv };

    // attn output (B,4,H,3)
    long ao = (t * 8 + h) * 3;
    attn_out[ao + 0] = a[0];
    attn_out[ao + 1] = a[1];
    attn_out[ao + 2] = a[2];

    // out = sum_l a_l * sigmoid(R_l) * V_l
    float O[32];
#pragma unroll
    for (int d = 0; d < 32; d++) O[d] = 0.f;
#pragma unroll
    for (int l = 0; l < 3; l++) {
        int nb = (l >= i) ? l + 1 : l;
        const float* vp = &g_P[((long)b * 4 + nb) * 1024 + 512 + h * 32];
        const float* rp = vp + 256;  // R slab is 768 offset = 512 + 256
        float al = a[l];
#pragma unroll
        for (int d4 = 0; d4 < 8; d4++) {
            float4 v = *(const float4*)&vp[d4 * 4];
            float4 r = *(const float4*)&rp[d4 * 4];
            O[d4 * 4 + 0] = fmaf(al * v.x, 1.f / (1.f + expf(-r.x)), O[d4 * 4 + 0]);
            O[d4 * 4 + 1] = fmaf(al * v.y, 1.f / (1.f + expf(-r.y)), O[d4 * 4 + 1]);
            O[d4 * 4 + 2] = fmaf(al * v.z, 1.f / (1.f + expf(-r.z)), O[d4 * 4 + 2]);
            O[d4 * 4 + 3] = fmaf(al * v.w, 1.f / (1.f + expf(-r.w)), O[d4 * 4 + 3]);
        }
    }
    float* op = &g_att[t * 256 + h * 32];
#pragma unroll
    for (int d4 = 0; d4 < 8; d4++)
        *(float4*)&op[d4 * 4] =
            make_float4(O[d4 * 4 + 0], O[d4 * 4 + 1], O[d4 * 4 + 2], O[d4 * 4 + 3]);
}

// ============================================================================
// K3: y = LN(tokens + g_att @ Wo^T) * gamma + beta
// BM=64, BN=256 (full row so LN is intra-block), BK=16; 256 threads, 8x8 micro.
// Warp w owns tokens [w*8, w*8+8) entirely -> shuffle reduction for mean/var.
// ============================================================================
__global__ __launch_bounds__(256)
void k_oproj_ln(const float* __restrict__ tok, const float* __restrict__ Wo,
                const float* __restrict__ gma, const float* __restrict__ bta,
                float* __restrict__ Y)
{
    __shared__ __align__(16) float As[16 * 64];    // [k][token]
    __shared__ __align__(16) float Bs[16 * 256];   // [k][out]

    const int tid = threadIdx.x;
    const long row0 = (long)blockIdx.x * 64;
    const int ty = tid >> 5;   // 8 token-groups of 8 (== warp id)
    const int tx = tid & 31;   // 32 out-groups of 8

    u64 acc[4][8];
#pragma unroll
    for (int i = 0; i < 4; i++)
#pragma unroll
        for (int u = 0; u < 8; u++) acc[i][u] = 0ULL;

    for (int k0 = 0; k0 < 256; k0 += 16) {
        // A tile 64x16: 256 float4, 1 per thread
        {
            int r = tid >> 2, c4 = tid & 3;
            float4 v = *(const float4*)&g_att[(row0 + r) * 256 + k0 + c4 * 4];
            As[(c4 * 4 + 0) * 64 + r] = v.x;
            As[(c4 * 4 + 1) * 64 + r] = v.y;
            As[(c4 * 4 + 2) * 64 + r] = v.z;
            As[(c4 * 4 + 3) * 64 + r] = v.w;
        }
        // B tile 256x16: 1024 float4, 4 per thread
#pragma unroll
        for (int s = 0; s < 4; s++) {
            int i = tid + s * 256;
            int r = i >> 2, c4 = i & 3;
            float4 v = *(const float4*)&Wo[r * 256 + k0 + c4 * 4];
            Bs[(c4 * 4 + 0) * 256 + r] = v.x;
            Bs[(c4 * 4 + 1) * 256 + r] = v.y;
            Bs[(c4 * 4 + 2) * 256 + r] = v.z;
            Bs[(c4 * 4 + 3) * 256 + r] = v.w;
        }
        __syncthreads();

#pragma unroll
        for (int kk = 0; kk < 16; kk++) {
            u64 a[4];
#pragma unroll
            for (int i = 0; i < 4; i++)
                a[i] = *(const u64*)&As[kk * 64 + ty * 8 + i * 2];
            float4 b0 = *(const float4*)&Bs[kk * 256 + tx * 8];
            float4 b1 = *(const float4*)&Bs[kk * 256 + tx * 8 + 4];
            u64 bb[8];
            bb[0] = pack2(b0.x, b0.x); bb[1] = pack2(b0.y, b0.y);
            bb[2] = pack2(b0.z, b0.z); bb[3] = pack2(b0.w, b0.w);
            bb[4] = pack2(b1.x, b1.x); bb[5] = pack2(b1.y, b1.y);
            bb[6] = pack2(b1.z, b1.z); bb[7] = pack2(b1.w, b1.w);
#pragma unroll
            for (int i = 0; i < 4; i++)
#pragma unroll
                for (int u = 0; u < 8; u++)
                    acc[i][u] = ffma2(a[i], bb[u], acc[i][u]);
        }
        __syncthreads();
    }

    // Unpack + residual
    float c[8][8];
#pragma unroll
    for (int i = 0; i < 4; i++)
#pragma unroll
        for (int u = 0; u < 8; u++)
            unpack2(acc[i][u], c[2 * i][u], c[2 * i + 1][u]);

    float4 g0 = *(const float4*)&gma[tx * 8];
    float4 g1 = *(const float4*)&gma[tx * 8 + 4];
    float4 bb0 = *(const float4*)&bta[tx * 8];
    float4 bb1 = *(const float4*)&bta[tx * 8 + 4];

#pragma unroll
    for (int tt = 0; tt < 8; tt++) {
        long trow = row0 + ty * 8 + tt;
        float4 r0 = *(const float4*)&tok[trow * 256 + tx * 8];
        float4 r1 = *(const float4*)&tok[trow * 256 + tx * 8 + 4];
        c[tt][0] += r0.x; c[tt][1] += r0.y; c[tt][2] += r0.z; c[tt][3] += r0.w;
        c[tt][4] += r1.x; c[tt][5] += r1.y; c[tt][6] += r1.z; c[tt][7] += r1.w;

        float ssum = 0.f, ssq = 0.f;
#pragma unroll
        for (int u = 0; u < 8; u++) { ssum += c[tt][u]; ssq += c[tt][u] * c[tt][u]; }
#pragma unroll
        for (int off = 16; off >= 1; off >>= 1) {
            ssum += __shfl_xor_sync(0xffffffffu, ssum, off);
            ssq  += __shfl_xor_sync(0xffffffffu, ssq, off);
        }
        float mu = ssum * (1.f / 256.f);
        float var = ssq * (1.f / 256.f) - mu * mu;
        float is = rsqrtf(var + 1e-5f);

        float y0 = (c[tt][0] - mu) * is * g0.x + bb0.x;
        float y1 = (c[tt][1] - mu) * is * g0.y + bb0.y;
        float y2 = (c[tt][2] - mu) * is * g0.z + bb0.z;
        float y3 = (c[tt][3] - mu) * is * g0.w + bb0.w;
        float y4 = (c[tt][4] - mu) * is * g1.x + bb1.x;
        float y5 = (c[tt][5] - mu) * is * g1.y + bb1.y;
        float y6 = (c[tt][6] - mu) * is * g1.z + bb1.z;
        float y7 = (c[tt][7] - mu) * is * g1.w + bb1.w;

        *(float4*)&Y[trow * 256 + tx * 8]     = make_float4(y0, y1, y2, y3);
        *(float4*)&Y[trow * 256 + tx * 8 + 4] = make_float4(y4, y5, y6, y7);
    }
}

// ============================================================================
extern "C" void kernel_launch(void* const* d_in, const int* in_sizes, int n_in,
                              void* d_out, int out_size)
{
    const float* tokens = (const float*)d_in[0];
    const float* Wq = (const float*)d_in[1];
    const float* Wk = (const float*)d_in[2];
    const float* Wv = (const float*)d_in[3];
    const float* Wr = (const float*)d_in[4];
    const float* Wo = (const float*)d_in[5];
    const float* ln_g = (const float*)d_in[6];
    const float* ln_b = (const float*)d_in[7];

    float* y = (float*)d_out;                       // (B,4,D) flattened
    float* attn = y + (size_t)NT * DD;              // (B,4,H,3) flattened after y

    k_gemm_qkvr<<<dim3(NT / 128, 8), 256>>>(tokens, Wq, Wk, Wv, Wr);
    k_attn<<<NB / 4, 128>>>(attn);
    k_oproj_ln<<<NT / 64, 256>>>(tokens, Wo, ln_g, ln_b, y);
}

// round 3
// speedup vs baseline: 2.1966x; 2.1966x over previous
#include <cuda_runtime.h>
#include <cuda_bf16.h>
#include <math.h>
#include <stdint.h>

#define NB 32768
#define NT (NB*4)              // 131072 tokens
#define KA 768                 // augmented K = [hi|lo|hi] * 256
#define QK_SCALE 0.17677669529663687f

// ---------------- scratch (static device globals) ---------------------------
__device__ __align__(16) __nv_bfloat16 g_Xp[(size_t)NT * KA];    // 201 MB
__device__ __align__(16) __nv_bfloat16 g_Wp[(size_t)1024 * KA];  // [Q|K|V|R]
__device__ __align__(16) __nv_bfloat16 g_Wop[(size_t)256 * KA];
__device__ __align__(16) float         g_P[(size_t)NT * 1024];   // QKVR f32
__device__ __align__(16) __nv_bfloat16 g_Ap[(size_t)NT * KA];    // attn out triple

// ---------------- PTX helpers ------------------------------------------------
__device__ __forceinline__ uint32_t smem_u32(const void* p) {
    uint32_t a;
    asm("{ .reg .u64 t; cvta.to.shared.u64 t, %1; cvt.u32.u64 %0, t; }" : "=r"(a) : "l"(p));
    return a;
}
__device__ __forceinline__ void cp16(uint32_t dst, const void* src) {
    asm volatile("cp.async.cg.shared.global [%0], [%1], 16;" :: "r"(dst), "l"(src) : "memory");
}
__device__ __forceinline__ void cp_commit() {
    asm volatile("cp.async.commit_group;" ::: "memory");
}
__device__ __forceinline__ void cp_wait1() {
    asm volatile("cp.async.wait_group 1;" ::: "memory");
}
__device__ __forceinline__ void ldm_x4(uint32_t* r, uint32_t addr) {
    asm volatile("ldmatrix.sync.aligned.m8n8.x4.shared.b16 {%0,%1,%2,%3}, [%4];"
                 : "=r"(r[0]), "=r"(r[1]), "=r"(r[2]), "=r"(r[3]) : "r"(addr));
}
__device__ __forceinline__ void mma16816(float* c, const uint32_t* a, uint32_t b0, uint32_t b1) {
    asm volatile(
        "mma.sync.aligned.m16n8k16.row.col.f32.bf16.bf16.f32 "
        "{%0,%1,%2,%3}, {%4,%5,%6,%7}, {%8,%9}, {%0,%1,%2,%3};"
        : "+f"(c[0]), "+f"(c[1]), "+f"(c[2]), "+f"(c[3])
        : "r"(a[0]), "r"(a[1]), "r"(a[2]), "r"(a[3]), "r"(b0), "r"(b1));
}

struct __align__(8) bf4 { __nv_bfloat162 a, b; };
__device__ __forceinline__ void split4(float4 v, bf4& hi, bf4& lo) {
    __nv_bfloat16 h0 = __float2bfloat16(v.x), h1 = __float2bfloat16(v.y);
    __nv_bfloat16 h2 = __float2bfloat16(v.z), h3 = __float2bfloat16(v.w);
    hi.a = __halves2bfloat162(h0, h1); hi.b = __halves2bfloat162(h2, h3);
    lo.a = __halves2bfloat162(__float2bfloat16(v.x - __bfloat162float(h0)),
                              __float2bfloat16(v.y - __bfloat162float(h1)));
    lo.b = __halves2bfloat162(__float2bfloat16(v.z - __bfloat162float(h2)),
                              __float2bfloat16(v.w - __bfloat162float(h3)));
}

// ============================================================================
// conversion kernels: fp32 -> bf16 triple [hi | lo | hi]
// ============================================================================
__global__ __launch_bounds__(256) void k_convX(const float* __restrict__ X) {
    long idx = (long)blockIdx.x * 256 + threadIdx.x;   // NT*64 items
    long t = idx >> 6; int col = (int)(idx & 63) * 4;
    float4 v = *(const float4*)(X + t * 256 + col);
    bf4 hi, lo; split4(v, hi, lo);
    __nv_bfloat16* row = g_Xp + t * KA;
    *(bf4*)(row + col)       = hi;
    *(bf4*)(row + 256 + col) = lo;
    *(bf4*)(row + 512 + col) = hi;
}

__global__ __launch_bounds__(256)
void k_convW(const float* __restrict__ Wq, const float* __restrict__ Wk,
             const float* __restrict__ Wv, const float* __restrict__ Wr,
             const float* __restrict__ Wo) {
    long idx = (long)blockIdx.x * 256 + threadIdx.x;   // 1280*64 items
    int j = (int)(idx >> 6); int col = (int)(idx & 63) * 4;
    const float* src; __nv_bfloat16* dst;
    if (j < 1024) {
        src = (j < 256) ? Wq : (j < 512) ? Wk : (j < 768) ? Wv : Wr;
        src += (size_t)(j & 255) * 256;
        dst = g_Wp + (size_t)j * KA;
    } else {
        src = Wo + (size_t)(j - 1024) * 256;
        dst = g_Wop + (size_t)(j - 1024) * KA;
    }
    float4 v = *(const float4*)(src + col);
    bf4 hi, lo; split4(v, hi, lo);
    *(bf4*)(dst + col)       = hi;   // pairs with A hi
    *(bf4*)(dst + 256 + col) = hi;   // pairs with A lo
    *(bf4*)(dst + 512 + col) = lo;   // pairs with A hi
}

// ---------------- shared tile helpers (64 bf16 = 8x16B chunks per row) -------
__device__ __forceinline__ uint32_t sw_off(int r, int c) {      // bytes
    return (uint32_t)((r * 8 + (c ^ (r & 7))) * 16);
}

// ============================================================================
// GEMM1: g_P[NT,1024] = g_Xp[NT,768] @ g_Wp[1024,768]^T
// CTA 128x128, BK=64, 8 warps (warp tile 32x64), 2-stage cp.async.
// grid = (8, 1024): x = N tile, y = M tile.
// ============================================================================
#define G1_A0 0
#define G1_B0 32768
#define G1_SMEM 65536

__global__ void __launch_bounds__(256) k_gemm1() {
    extern __shared__ __align__(1024) char smem[];
    const uint32_t sb = smem_u32(smem);
    const int tid = threadIdx.x;
    const int l = tid & 31, w = tid >> 5;
    const int wm = w & 3, wn = w >> 2;          // warp tile: rows wm*32, cols wn*64
    const int n0 = blockIdx.x * 128;
    const size_t row0 = (size_t)blockIdx.y * 128;

    const int lr = tid >> 3, lc = tid & 7;      // loader: row lr(+64s), chunk lc

    float acc[2][8][4];
#pragma unroll
    for (int i = 0; i < 2; i++)
#pragma unroll
        for (int j = 0; j < 8; j++)
#pragma unroll
            for (int k = 0; k < 4; k++) acc[i][j][k] = 0.f;

    // ---- stage issue: A 128x64, B 128x64 (4 cp each) ----
    auto issue = [&](int s, int buf) {
        const int k0 = s * 64;
        const uint32_t sa = sb + G1_A0 + buf * 16384;
        const uint32_t sbm = sb + G1_B0 + buf * 16384;
#pragma unroll
        for (int u = 0; u < 4; u++) {
            int r = lr + u * 32;
            cp16(sa + sw_off(r, lc), g_Xp + (row0 + r) * KA + k0 + lc * 8);
        }
#pragma unroll
        for (int u = 0; u < 4; u++) {
            int r = lr + u * 32;
            cp16(sbm + sw_off(r, lc), g_Wp + (size_t)(n0 + r) * KA + k0 + lc * 8);
        }
    };

    issue(0, 0); cp_commit();

    for (int s = 0; s < 12; s++) {
        if (s + 1 < 12) issue(s + 1, (s + 1) & 1);
        cp_commit();
        cp_wait1();
        __syncthreads();

        const uint32_t sa = sb + G1_A0 + (s & 1) * 16384;
        const uint32_t sbm = sb + G1_B0 + (s & 1) * 16384;
#pragma unroll
        for (int ks = 0; ks < 4; ks++) {
            uint32_t a[2][4], b[4][4];
            const int cc = ks * 2 + (l >> 4);
#pragma unroll
            for (int mi = 0; mi < 2; mi++) {
                int r = wm * 32 + mi * 16 + (l & 15);
                ldm_x4(a[mi], sa + sw_off(r, cc));
            }
#pragma unroll
            for (int ni = 0; ni < 4; ni++) {
                int r = wn * 64 + ni * 16 + (l & 15);
                ldm_x4(b[ni], sbm + sw_off(r, cc));
            }
#pragma unroll
            for (int mi = 0; mi < 2; mi++)
#pragma unroll
                for (int ni = 0; ni < 4; ni++) {
                    mma16816(acc[mi][ni * 2],     a[mi], b[ni][0], b[ni][2]);
                    mma16816(acc[mi][ni * 2 + 1], a[mi], b[ni][1], b[ni][3]);
                }
        }
        __syncthreads();
    }

    // ---- epilogue: write f32 to g_P ----
#pragma unroll
    for (int mi = 0; mi < 2; mi++) {
        size_t rbase = row0 + wm * 32 + mi * 16 + (l >> 2);
#pragma unroll
        for (int ni = 0; ni < 8; ni++) {
            int col = n0 + wn * 64 + ni * 8 + (l & 3) * 2;
            *(float2*)(g_P + rbase * 1024 + col) =
                make_float2(acc[mi][ni][0], acc[mi][ni][1]);
            *(float2*)(g_P + (rbase + 8) * 1024 + col) =
                make_float2(acc[mi][ni][2], acc[mi][ni][3]);
        }
    }
}

// ============================================================================
// attention: warp per sample; writes attn probs + g_Ap bf16 triple
// ============================================================================
__global__ __launch_bounds__(128)
void k_attn(float* __restrict__ attn_out)
{
    const int b = blockIdx.x * 4 + (threadIdx.x >> 5);
    const int lane = threadIdx.x & 31;
    const int i = lane >> 3;
    const int h = lane & 7;
    const size_t t = (size_t)b * 4 + i;

    float Q[32];
    const float* qp = &g_P[t * 1024 + h * 32];
#pragma unroll
    for (int d4 = 0; d4 < 8; d4++) {
        float4 v = *(const float4*)&qp[d4 * 4];
        Q[d4*4+0] = v.x; Q[d4*4+1] = v.y; Q[d4*4+2] = v.z; Q[d4*4+3] = v.w;
    }

    float s[3];
#pragma unroll
    for (int lix = 0; lix < 3; lix++) {
        int nb = (lix >= i) ? lix + 1 : lix;
        const float* kp = &g_P[((size_t)b * 4 + nb) * 1024 + 256 + h * 32];
        float acc = 0.f;
#pragma unroll
        for (int d4 = 0; d4 < 8; d4++) {
            float4 v = *(const float4*)&kp[d4 * 4];
            acc = fmaf(Q[d4*4+0], v.x, acc); acc = fmaf(Q[d4*4+1], v.y, acc);
            acc = fmaf(Q[d4*4+2], v.z, acc); acc = fmaf(Q[d4*4+3], v.w, acc);
        }
        s[lix] = acc * QK_SCALE;
    }

    float m = fmaxf(s[0], fmaxf(s[1], s[2]));
    float e0 = expf(s[0]-m), e1 = expf(s[1]-m), e2 = expf(s[2]-m);
    float inv = 1.f / (e0 + e1 + e2);
    float a[3] = { e0*inv, e1*inv, e2*inv };

    size_t ao = (t * 8 + h) * 3;
    attn_out[ao+0] = a[0]; attn_out[ao+1] = a[1]; attn_out[ao+2] = a[2];

    float O[32];
#pragma unroll
    for (int d = 0; d < 32; d++) O[d] = 0.f;
#pragma unroll
    for (int lix = 0; lix < 3; lix++) {
        int nb = (lix >= i) ? lix + 1 : lix;
        const float* vp = &g_P[((size_t)b * 4 + nb) * 1024 + 512 + h * 32];
        const float* rp = vp + 256;
        float al = a[lix];
#pragma unroll
        for (int d4 = 0; d4 < 8; d4++) {
            float4 v = *(const float4*)&vp[d4 * 4];
            float4 r = *(const float4*)&rp[d4 * 4];
            O[d4*4+0] = fmaf(al * v.x, 1.f/(1.f+expf(-r.x)), O[d4*4+0]);
            O[d4*4+1] = fmaf(al * v.y, 1.f/(1.f+expf(-r.y)), O[d4*4+1]);
            O[d4*4+2] = fmaf(al * v.z, 1.f/(1.f+expf(-r.z)), O[d4*4+2]);
            O[d4*4+3] = fmaf(al * v.w, 1.f/(1.f+expf(-r.w)), O[d4*4+3]);
        }
    }
    __nv_bfloat16* row = g_Ap + t * KA + h * 32;
#pragma unroll
    for (int d4 = 0; d4 < 8; d4++) {
        float4 v = make_float4(O[d4*4+0], O[d4*4+1], O[d4*4+2], O[d4*4+3]);
        bf4 hi, lo; split4(v, hi, lo);
        *(bf4*)(row + d4*4)       = hi;
        *(bf4*)(row + 256 + d4*4) = lo;
        *(bf4*)(row + 512 + d4*4) = hi;
    }
}

// ============================================================================
// GEMM2 + residual + LN: y = LN(tok + g_Ap @ g_Wop^T)
// CTA 64x256, BK=64, 8 warps (warp tile 32x64, 2x4 layout), 2-stage cp.async.
// LN via SMEM staging of the 64x256 accum tile.
// ============================================================================
#define G2_A0 0
#define G2_B0 16384
#define G2_SMEM 81920

__global__ void __launch_bounds__(256)
k_gemm2(const float* __restrict__ tok, const float* __restrict__ gma,
        const float* __restrict__ bta, float* __restrict__ Y)
{
    extern __shared__ __align__(1024) char smem[];
    const uint32_t sb = smem_u32(smem);
    const int tid = threadIdx.x;
    const int l = tid & 31, w = tid >> 5;
    const int wm = w & 1, wn = w >> 1;          // warp tile: rows wm*32, cols wn*64
    const size_t row0 = (size_t)blockIdx.x * 64;

    const int lr = tid >> 3, lc = tid & 7;

    float acc[2][8][4];
#pragma unroll
    for (int i = 0; i < 2; i++)
#pragma unroll
        for (int j = 0; j < 8; j++)
#pragma unroll
            for (int k = 0; k < 4; k++) acc[i][j][k] = 0.f;

    auto issue = [&](int s, int buf) {
        const int k0 = s * 64;
        const uint32_t sa = sb + G2_A0 + buf * 8192;
        const uint32_t sbm = sb + G2_B0 + buf * 32768;
#pragma unroll
        for (int u = 0; u < 2; u++) {
            int r = lr + u * 32;
            cp16(sa + sw_off(r, lc), g_Ap + (row0 + r) * KA + k0 + lc * 8);
        }
#pragma unroll
        for (int u = 0; u < 8; u++) {
            int r = lr + u * 32;
            cp16(sbm + sw_off(r, lc), g_Wop + (size_t)r * KA + k0 + lc * 8);
        }
    };

    issue(0, 0); cp_commit();

    for (int s = 0; s < 12; s++) {
        if (s + 1 < 12) issue(s + 1, (s + 1) & 1);
        cp_commit();
        cp_wait1();
        __syncthreads();

        const uint32_t sa = sb + G2_A0 + (s & 1) * 8192;
        const uint32_t sbm = sb + G2_B0 + (s & 1) * 32768;
#pragma unroll
        for (int ks = 0; ks < 4; ks++) {
            uint32_t a[2][4], b[4][4];
            const int cc = ks * 2 + (l >> 4);
#pragma unroll
            for (int mi = 0; mi < 2; mi++) {
                int r = wm * 32 + mi * 16 + (l & 15);
                ldm_x4(a[mi], sa + sw_off(r, cc));
            }
#pragma unroll
            for (int ni = 0; ni < 4; ni++) {
                int r = wn * 64 + ni * 16 + (l & 15);
                ldm_x4(b[ni], sbm + sw_off(r, cc));
            }
#pragma unroll
            for (int mi = 0; mi < 2; mi++)
#pragma unroll
                for (int ni = 0; ni < 4; ni++) {
                    mma16816(acc[mi][ni * 2],     a[mi], b[ni][0], b[ni][2]);
                    mma16816(acc[mi][ni * 2 + 1], a[mi], b[ni][1], b[ni][3]);
                }
        }
        __syncthreads();
    }

    // ---- stage accum tile into SMEM (64 x 260 f32, padded) ----
    float* sred = (float*)smem;
    __syncthreads();
#pragma unroll
    for (int mi = 0; mi < 2; mi++) {
        int rb = wm * 32 + mi * 16 + (l >> 2);
#pragma unroll
        for (int ni = 0; ni < 8; ni++) {
            int col = wn * 64 + ni * 8 + (l & 3) * 2;
            *(float2*)(sred + rb * 260 + col) = make_float2(acc[mi][ni][0], acc[mi][ni][1]);
            *(float2*)(sred + (rb + 8) * 260 + col) = make_float2(acc[mi][ni][2], acc[mi][ni][3]);
        }
    }
    __syncthreads();

    // ---- LN: warp w handles rows w*8 .. w*8+8; lane covers 8 cols ----
#pragma unroll
    for (int rr = 0; rr < 8; rr++) {
        int row = w * 8 + rr;
        size_t grow = row0 + row;
        float v[8];
        float4 t0 = *(const float4*)(tok + grow * 256 + l * 8);
        float4 t1 = *(const float4*)(tok + grow * 256 + l * 8 + 4);
        float4 s0 = *(const float4*)(sred + row * 260 + l * 8);
        float4 s1 = *(const float4*)(sred + row * 260 + l * 8 + 4);
        v[0] = s0.x + t0.x; v[1] = s0.y + t0.y; v[2] = s0.z + t0.z; v[3] = s0.w + t0.w;
        v[4] = s1.x + t1.x; v[5] = s1.y + t1.y; v[6] = s1.z + t1.z; v[7] = s1.w + t1.w;

        float sum = 0.f, sq = 0.f;
#pragma unroll
        for (int u = 0; u < 8; u++) { sum += v[u]; sq += v[u] * v[u]; }
#pragma unroll
        for (int off = 16; off >= 1; off >>= 1) {
            sum += __shfl_xor_sync(0xffffffffu, sum, off);
            sq  += __shfl_xor_sync(0xffffffffu, sq, off);
        }
        float mu = sum * (1.f / 256.f);
        float var = sq * (1.f / 256.f) - mu * mu;
        float is = rsqrtf(var + 1e-5f);

        float4 g0 = *(const float4*)(gma + l * 8);
        float4 g1 = *(const float4*)(gma + l * 8 + 4);
        float4 b0 = *(const float4*)(bta + l * 8);
        float4 b1 = *(const float4*)(bta + l * 8 + 4);
        *(float4*)(Y + grow * 256 + l * 8) = make_float4(
            (v[0]-mu)*is*g0.x + b0.x, (v[1]-mu)*is*g0.y + b0.y,
            (v[2]-mu)*is*g0.z + b0.z, (v[3]-mu)*is*g0.w + b0.w);
        *(float4*)(Y + grow * 256 + l * 8 + 4) = make_float4(
            (v[4]-mu)*is*g1.x + b1.x, (v[5]-mu)*is*g1.y + b1.y,
            (v[6]-mu)*is*g1.z + b1.z, (v[7]-mu)*is*g1.w + b1.w);
    }
}

// ============================================================================
extern "C" void kernel_launch(void* const* d_in, const int* in_sizes, int n_in,
                              void* d_out, int out_size)
{
    const float* tokens = (const float*)d_in[0];
    const float* Wq = (const float*)d_in[1];
    const float* Wk = (const float*)d_in[2];
    const float* Wv = (const float*)d_in[3];
    const float* Wr = (const float*)d_in[4];
    const float* Wo = (const float*)d_in[5];
    const float* ln_g = (const float*)d_in[6];
    const float* ln_b = (const float*)d_in[7];

    float* y = (float*)d_out;
    float* attn = y + (size_t)NT * 256;

    static int configured = 0;
    if (!configured) {
        cudaFuncSetAttribute(k_gemm1, cudaFuncAttributeMaxDynamicSharedMemorySize, G1_SMEM);
        cudaFuncSetAttribute(k_gemm2, cudaFuncAttributeMaxDynamicSharedMemorySize, G2_SMEM);
        configured = 1;
    }

    k_convX<<<NT * 64 / 256, 256>>>(tokens);
    k_convW<<<1280 * 64 / 256, 256>>>(Wq, Wk, Wv, Wr, Wo);
    k_gemm1<<<dim3(8, 1024), 256, G1_SMEM>>>();
    k_attn<<<NB / 4, 128>>>(attn);
    k_gemm2<<<NT / 64, 256, G2_SMEM>>>(tokens, ln_g, ln_b, y);
}

// round 4
// speedup vs baseline: 2.5450x; 1.1586x over previous
#include <cuda_runtime.h>
#include <cuda_bf16.h>
#include <math.h>
#include <stdint.h>

#define NB 32768
#define NT (NB*4)              // 131072 tokens
#define KA 768                 // augmented K = [hi|lo|hi] * 256
#define QK_SCALE 0.17677669529663687f

// ---------------- scratch (static device globals) ---------------------------
__device__ __align__(16) __nv_bfloat16 g_Xp[(size_t)NT * KA];    // 201 MB
__device__ __align__(16) __nv_bfloat16 g_Wp[(size_t)1024 * KA];  // [Q|K|V|R]
__device__ __align__(16) __nv_bfloat16 g_Wop[(size_t)256 * KA];
__device__ __align__(16) float         g_P[(size_t)NT * 1024];   // QKVR f32
__device__ __align__(16) __nv_bfloat16 g_Ap[(size_t)NT * KA];    // attn out triple

// ---------------- PTX helpers ------------------------------------------------
__device__ __forceinline__ uint32_t smem_u32(const void* p) {
    uint32_t a;
    asm("{ .reg .u64 t; cvta.to.shared.u64 t, %1; cvt.u32.u64 %0, t; }" : "=r"(a) : "l"(p));
    return a;
}
__device__ __forceinline__ void cp16(uint32_t dst, const void* src) {
    asm volatile("cp.async.cg.shared.global [%0], [%1], 16;" :: "r"(dst), "l"(src) : "memory");
}
__device__ __forceinline__ void cp_commit() {
    asm volatile("cp.async.commit_group;" ::: "memory");
}
__device__ __forceinline__ void cp_wait1() {
    asm volatile("cp.async.wait_group 1;" ::: "memory");
}
__device__ __forceinline__ void ldm_x4(uint32_t* r, uint32_t addr) {
    asm volatile("ldmatrix.sync.aligned.m8n8.x4.shared.b16 {%0,%1,%2,%3}, [%4];"
                 : "=r"(r[0]), "=r"(r[1]), "=r"(r[2]), "=r"(r[3]) : "r"(addr));
}
__device__ __forceinline__ void mma16816(float* c, const uint32_t* a, uint32_t b0, uint32_t b1) {
    asm volatile(
        "mma.sync.aligned.m16n8k16.row.col.f32.bf16.bf16.f32 "
        "{%0,%1,%2,%3}, {%4,%5,%6,%7}, {%8,%9}, {%0,%1,%2,%3};"
        : "+f"(c[0]), "+f"(c[1]), "+f"(c[2]), "+f"(c[3])
        : "r"(a[0]), "r"(a[1]), "r"(a[2]), "r"(a[3]), "r"(b0), "r"(b1));
}

struct __align__(8) bf4 { __nv_bfloat162 a, b; };
__device__ __forceinline__ void split4(float4 v, bf4& hi, bf4& lo) {
    __nv_bfloat16 h0 = __float2bfloat16(v.x), h1 = __float2bfloat16(v.y);
    __nv_bfloat16 h2 = __float2bfloat16(v.z), h3 = __float2bfloat16(v.w);
    hi.a = __halves2bfloat162(h0, h1); hi.b = __halves2bfloat162(h2, h3);
    lo.a = __halves2bfloat162(__float2bfloat16(v.x - __bfloat162float(h0)),
                              __float2bfloat16(v.y - __bfloat162float(h1)));
    lo.b = __halves2bfloat162(__float2bfloat16(v.z - __bfloat162float(h2)),
                              __float2bfloat16(v.w - __bfloat162float(h3)));
}

// ============================================================================
// conversion kernels: fp32 -> bf16 triple [hi | lo | hi]
// ============================================================================
__global__ __launch_bounds__(256) void k_convX(const float* __restrict__ X) {
    long idx = (long)blockIdx.x * 256 + threadIdx.x;   // NT*64 items
    long t = idx >> 6; int col = (int)(idx & 63) * 4;
    float4 v = *(const float4*)(X + t * 256 + col);
    bf4 hi, lo; split4(v, hi, lo);
    __nv_bfloat16* row = g_Xp + t * KA;
    *(bf4*)(row + col)       = hi;
    *(bf4*)(row + 256 + col) = lo;
    *(bf4*)(row + 512 + col) = hi;
}

__global__ __launch_bounds__(256)
void k_convW(const float* __restrict__ Wq, const float* __restrict__ Wk,
             const float* __restrict__ Wv, const float* __restrict__ Wr,
             const float* __restrict__ Wo) {
    long idx = (long)blockIdx.x * 256 + threadIdx.x;   // 1280*64 items
    int j = (int)(idx >> 6); int col = (int)(idx & 63) * 4;
    const float* src; __nv_bfloat16* dst;
    if (j < 1024) {
        src = (j < 256) ? Wq : (j < 512) ? Wk : (j < 768) ? Wv : Wr;
        src += (size_t)(j & 255) * 256;
        dst = g_Wp + (size_t)j * KA;
    } else {
        src = Wo + (size_t)(j - 1024) * 256;
        dst = g_Wop + (size_t)(j - 1024) * KA;
    }
    float4 v = *(const float4*)(src + col);
    bf4 hi, lo; split4(v, hi, lo);
    *(bf4*)(dst + col)       = hi;   // pairs with A hi
    *(bf4*)(dst + 256 + col) = hi;   // pairs with A lo
    *(bf4*)(dst + 512 + col) = lo;   // pairs with A hi
}

// ---------------- shared tile helpers (64 bf16 = 8x16B chunks per row) -------
__device__ __forceinline__ uint32_t sw_off(int r, int c) {      // bytes
    return (uint32_t)((r * 8 + (c ^ (r & 7))) * 16);
}

// ============================================================================
// GEMM1: g_P[NT,1024] = g_Xp[NT,768] @ g_Wp[1024,768]^T
// CTA 128x128, BK=64, 8 warps (warp tile 32x64), 2-stage cp.async.
// ============================================================================
#define G1_A0 0
#define G1_B0 32768
#define G1_SMEM 65536

__global__ void __launch_bounds__(256) k_gemm1() {
    extern __shared__ __align__(1024) char smem[];
    const uint32_t sb = smem_u32(smem);
    const int tid = threadIdx.x;
    const int l = tid & 31, w = tid >> 5;
    const int wm = w & 3, wn = w >> 2;
    const int n0 = blockIdx.x * 128;
    const size_t row0 = (size_t)blockIdx.y * 128;

    const int lr = tid >> 3, lc = tid & 7;

    float acc[2][8][4];
#pragma unroll
    for (int i = 0; i < 2; i++)
#pragma unroll
        for (int j = 0; j < 8; j++)
#pragma unroll
            for (int k = 0; k < 4; k++) acc[i][j][k] = 0.f;

    auto issue = [&](int s, int buf) {
        const int k0 = s * 64;
        const uint32_t sa = sb + G1_A0 + buf * 16384;
        const uint32_t sbm = sb + G1_B0 + buf * 16384;
#pragma unroll
        for (int u = 0; u < 4; u++) {
            int r = lr + u * 32;
            cp16(sa + sw_off(r, lc), g_Xp + (row0 + r) * KA + k0 + lc * 8);
        }
#pragma unroll
        for (int u = 0; u < 4; u++) {
            int r = lr + u * 32;
            cp16(sbm + sw_off(r, lc), g_Wp + (size_t)(n0 + r) * KA + k0 + lc * 8);
        }
    };

    issue(0, 0); cp_commit();

    for (int s = 0; s < 12; s++) {
        if (s + 1 < 12) issue(s + 1, (s + 1) & 1);
        cp_commit();
        cp_wait1();
        __syncthreads();

        const uint32_t sa = sb + G1_A0 + (s & 1) * 16384;
        const uint32_t sbm = sb + G1_B0 + (s & 1) * 16384;
#pragma unroll
        for (int ks = 0; ks < 4; ks++) {
            uint32_t a[2][4], b[4][4];
            const int cc = ks * 2 + (l >> 4);
#pragma unroll
            for (int mi = 0; mi < 2; mi++) {
                int r = wm * 32 + mi * 16 + (l & 15);
                ldm_x4(a[mi], sa + sw_off(r, cc));
            }
#pragma unroll
            for (int ni = 0; ni < 4; ni++) {
                int r = wn * 64 + ni * 16 + (l & 15);
                ldm_x4(b[ni], sbm + sw_off(r, cc));
            }
#pragma unroll
            for (int mi = 0; mi < 2; mi++)
#pragma unroll
                for (int ni = 0; ni < 4; ni++) {
                    mma16816(acc[mi][ni * 2],     a[mi], b[ni][0], b[ni][2]);
                    mma16816(acc[mi][ni * 2 + 1], a[mi], b[ni][1], b[ni][3]);
                }
        }
        __syncthreads();
    }

#pragma unroll
    for (int mi = 0; mi < 2; mi++) {
        size_t rbase = row0 + wm * 32 + mi * 16 + (l >> 2);
#pragma unroll
        for (int ni = 0; ni < 8; ni++) {
            int col = n0 + wn * 64 + ni * 8 + (l & 3) * 2;
            *(float2*)(g_P + rbase * 1024 + col) =
                make_float2(acc[mi][ni][0], acc[mi][ni][1]);
            *(float2*)(g_P + (rbase + 8) * 1024 + col) =
                make_float2(acc[mi][ni][2], acc[mi][ni][3]);
        }
    }
}

// ============================================================================
// attention v2: 8 warps/block, one sample per warp.
// Phase 1: coalesced staging of K and V_eff=sigmoid(R)*V into SMEM.
// Phase 2: lane (i,h) scores/softmax/output from SMEM.
// ============================================================================
#define APAD 36                        // floats per head slot in SMEM
#define TOKSTRIDE (8 * APAD)           // 288 floats per token
#define WARPSM (2 * 4 * TOKSTRIDE)     // 2304 floats per warp (K + V_eff)
#define ATTN_SMEM (8 * WARPSM * 4)     // 73728 B

__global__ void __launch_bounds__(256) k_attn(float* __restrict__ attn_out)
{
    extern __shared__ __align__(16) float sm[];
    const int wid = threadIdx.x >> 5;
    const int lane = threadIdx.x & 31;
    const int b = blockIdx.x * 8 + wid;
    float* sK = sm + wid * WARPSM;
    float* sV = sK + 4 * TOKSTRIDE;
    const size_t rowb = (size_t)b * 4;

    // ---- phase 1: stage K, compute V_eff once per token ----
#pragma unroll
    for (int i = 0; i < 4; i++) {
        const float* base = g_P + (rowb + i) * 1024;
#pragma unroll
        for (int c = 0; c < 2; c++) {
            int o = (c * 32 + lane) * 4;     // 0..252, step 4
            int h = o >> 5, d = o & 31;
            float4 k4 = *(const float4*)(base + 256 + o);
            *(float4*)(sK + (i * 8 + h) * APAD + d) = k4;
            float4 v4 = *(const float4*)(base + 512 + o);
            float4 r4 = *(const float4*)(base + 768 + o);
            float4 ve;
            ve.x = v4.x / (1.f + __expf(-r4.x));
            ve.y = v4.y / (1.f + __expf(-r4.y));
            ve.z = v4.z / (1.f + __expf(-r4.z));
            ve.w = v4.w / (1.f + __expf(-r4.w));
            *(float4*)(sV + (i * 8 + h) * APAD + d) = ve;
        }
    }
    __syncwarp();

    // ---- phase 2: per-lane (i,h) attention ----
    const int i = lane >> 3;
    const int h = lane & 7;
    const size_t t = rowb + i;

    float4 Q[8];
    const float* qp = g_P + t * 1024 + h * 32;
#pragma unroll
    for (int c = 0; c < 8; c++) Q[c] = *(const float4*)(qp + c * 4);

    float s[3];
#pragma unroll
    for (int lix = 0; lix < 3; lix++) {
        int nb = (lix >= i) ? lix + 1 : lix;
        const float* kp = sK + (nb * 8 + h) * APAD;
        float a0 = 0.f, a1 = 0.f;
#pragma unroll
        for (int c = 0; c < 4; c++) {
            float4 k0 = *(const float4*)(kp + c * 8);
            float4 k1 = *(const float4*)(kp + c * 8 + 4);
            float4 q0 = Q[c * 2], q1 = Q[c * 2 + 1];
            a0 = fmaf(q0.x, k0.x, a0); a0 = fmaf(q0.y, k0.y, a0);
            a0 = fmaf(q0.z, k0.z, a0); a0 = fmaf(q0.w, k0.w, a0);
            a1 = fmaf(q1.x, k1.x, a1); a1 = fmaf(q1.y, k1.y, a1);
            a1 = fmaf(q1.z, k1.z, a1); a1 = fmaf(q1.w, k1.w, a1);
        }
        s[lix] = (a0 + a1) * QK_SCALE;
    }

    float m = fmaxf(s[0], fmaxf(s[1], s[2]));
    float e0 = __expf(s[0] - m), e1 = __expf(s[1] - m), e2 = __expf(s[2] - m);
    float inv = 1.f / (e0 + e1 + e2);
    float a[3] = { e0 * inv, e1 * inv, e2 * inv };

    size_t ao = (t * 8 + h) * 3;
    attn_out[ao + 0] = a[0]; attn_out[ao + 1] = a[1]; attn_out[ao + 2] = a[2];

    float O[32];
#pragma unroll
    for (int d = 0; d < 32; d++) O[d] = 0.f;
#pragma unroll
    for (int lix = 0; lix < 3; lix++) {
        int nb = (lix >= i) ? lix + 1 : lix;
        const float* vp = sV + (nb * 8 + h) * APAD;
        float al = a[lix];
#pragma unroll
        for (int c = 0; c < 8; c++) {
            float4 v = *(const float4*)(vp + c * 4);
            O[c*4+0] = fmaf(al, v.x, O[c*4+0]);
            O[c*4+1] = fmaf(al, v.y, O[c*4+1]);
            O[c*4+2] = fmaf(al, v.z, O[c*4+2]);
            O[c*4+3] = fmaf(al, v.w, O[c*4+3]);
        }
    }
    __nv_bfloat16* row = g_Ap + t * KA + h * 32;
#pragma unroll
    for (int d4 = 0; d4 < 8; d4++) {
        float4 v = make_float4(O[d4*4+0], O[d4*4+1], O[d4*4+2], O[d4*4+3]);
        bf4 hi, lo; split4(v, hi, lo);
        *(bf4*)(row + d4*4)       = hi;
        *(bf4*)(row + 256 + d4*4) = lo;
        *(bf4*)(row + 512 + d4*4) = hi;
    }
}

// ============================================================================
// GEMM2 + residual + LN: y = LN(tok + g_Ap @ g_Wop^T)
// ============================================================================
#define G2_A0 0
#define G2_B0 16384
#define G2_SMEM 81920

__global__ void __launch_bounds__(256)
k_gemm2(const float* __restrict__ tok, const float* __restrict__ gma,
        const float* __restrict__ bta, float* __restrict__ Y)
{
    extern __shared__ __align__(1024) char smem[];
    const uint32_t sb = smem_u32(smem);
    const int tid = threadIdx.x;
    const int l = tid & 31, w = tid >> 5;
    const int wm = w & 1, wn = w >> 1;
    const size_t row0 = (size_t)blockIdx.x * 64;

    const int lr = tid >> 3, lc = tid & 7;

    float acc[2][8][4];
#pragma unroll
    for (int i = 0; i < 2; i++)
#pragma unroll
        for (int j = 0; j < 8; j++)
#pragma unroll
            for (int k = 0; k < 4; k++) acc[i][j][k] = 0.f;

    auto issue = [&](int s, int buf) {
        const int k0 = s * 64;
        const uint32_t sa = sb + G2_A0 + buf * 8192;
        const uint32_t sbm = sb + G2_B0 + buf * 32768;
#pragma unroll
        for (int u = 0; u < 2; u++) {
            int r = lr + u * 32;
            cp16(sa + sw_off(r, lc), g_Ap + (row0 + r) * KA + k0 + lc * 8);
        }
#pragma unroll
        for (int u = 0; u < 8; u++) {
            int r = lr + u * 32;
            cp16(sbm + sw_off(r, lc), g_Wop + (size_t)r * KA + k0 + lc * 8);
        }
    };

    issue(0, 0); cp_commit();

    for (int s = 0; s < 12; s++) {
        if (s + 1 < 12) issue(s + 1, (s + 1) & 1);
        cp_commit();
        cp_wait1();
        __syncthreads();

        const uint32_t sa = sb + G2_A0 + (s & 1) * 8192;
        const uint32_t sbm = sb + G2_B0 + (s & 1) * 32768;
#pragma unroll
        for (int ks = 0; ks < 4; ks++) {
            uint32_t a[2][4], b[4][4];
            const int cc = ks * 2 + (l >> 4);
#pragma unroll
            for (int mi = 0; mi < 2; mi++) {
                int r = wm * 32 + mi * 16 + (l & 15);
                ldm_x4(a[mi], sa + sw_off(r, cc));
            }
#pragma unroll
            for (int ni = 0; ni < 4; ni++) {
                int r = wn * 64 + ni * 16 + (l & 15);
                ldm_x4(b[ni], sbm + sw_off(r, cc));
            }
#pragma unroll
            for (int mi = 0; mi < 2; mi++)
#pragma unroll
                for (int ni = 0; ni < 4; ni++) {
                    mma16816(acc[mi][ni * 2],     a[mi], b[ni][0], b[ni][2]);
                    mma16816(acc[mi][ni * 2 + 1], a[mi], b[ni][1], b[ni][3]);
                }
        }
        __syncthreads();
    }

    float* sred = (float*)smem;
    __syncthreads();
#pragma unroll
    for (int mi = 0; mi < 2; mi++) {
        int rb = wm * 32 + mi * 16 + (l >> 2);
#pragma unroll
        for (int ni = 0; ni < 8; ni++) {
            int col = wn * 64 + ni * 8 + (l & 3) * 2;
            *(float2*)(sred + rb * 260 + col) = make_float2(acc[mi][ni][0], acc[mi][ni][1]);
            *(float2*)(sred + (rb + 8) * 260 + col) = make_float2(acc[mi][ni][2], acc[mi][ni][3]);
        }
    }
    __syncthreads();

#pragma unroll
    for (int rr = 0; rr < 8; rr++) {
        int row = w * 8 + rr;
        size_t grow = row0 + row;
        float v[8];
        float4 t0 = *(const float4*)(tok + grow * 256 + l * 8);
        float4 t1 = *(const float4*)(tok + grow * 256 + l * 8 + 4);
        float4 s0 = *(const float4*)(sred + row * 260 + l * 8);
        float4 s1 = *(const float4*)(sred + row * 260 + l * 8 + 4);
        v[0] = s0.x + t0.x; v[1] = s0.y + t0.y; v[2] = s0.z + t0.z; v[3] = s0.w + t0.w;
        v[4] = s1.x + t1.x; v[5] = s1.y + t1.y; v[6] = s1.z + t1.z; v[7] = s1.w + t1.w;

        float sum = 0.f, sq = 0.f;
#pragma unroll
        for (int u = 0; u < 8; u++) { sum += v[u]; sq += v[u] * v[u]; }
#pragma unroll
        for (int off = 16; off >= 1; off >>= 1) {
            sum += __shfl_xor_sync(0xffffffffu, sum, off);
            sq  += __shfl_xor_sync(0xffffffffu, sq, off);
        }
        float mu = sum * (1.f / 256.f);
        float var = sq * (1.f / 256.f) - mu * mu;
        float is = rsqrtf(var + 1e-5f);

        float4 g0 = *(const float4*)(gma + l * 8);
        float4 g1 = *(const float4*)(gma + l * 8 + 4);
        float4 b0 = *(const float4*)(bta + l * 8);
        float4 b1 = *(const float4*)(bta + l * 8 + 4);
        *(float4*)(Y + grow * 256 + l * 8) = make_float4(
            (v[0]-mu)*is*g0.x + b0.x, (v[1]-mu)*is*g0.y + b0.y,
            (v[2]-mu)*is*g0.z + b0.z, (v[3]-mu)*is*g0.w + b0.w);
        *(float4*)(Y + grow * 256 + l * 8 + 4) = make_float4(
            (v[4]-mu)*is*g1.x + b1.x, (v[5]-mu)*is*g1.y + b1.y,
            (v[6]-mu)*is*g1.z + b1.z, (v[7]-mu)*is*g1.w + b1.w);
    }
}

// ============================================================================
extern "C" void kernel_launch(void* const* d_in, const int* in_sizes, int n_in,
                              void* d_out, int out_size)
{
    const float* tokens = (const float*)d_in[0];
    const float* Wq = (const float*)d_in[1];
    const float* Wk = (const float*)d_in[2];
    const float* Wv = (const float*)d_in[3];
    const float* Wr = (const float*)d_in[4];
    const float* Wo = (const float*)d_in[5];
    const float* ln_g = (const float*)d_in[6];
    const float* ln_b = (const float*)d_in[7];

    float* y = (float*)d_out;
    float* attn = y + (size_t)NT * 256;

    static int configured = 0;
    if (!configured) {
        cudaFuncSetAttribute(k_gemm1, cudaFuncAttributeMaxDynamicSharedMemorySize, G1_SMEM);
        cudaFuncSetAttribute(k_gemm2, cudaFuncAttributeMaxDynamicSharedMemorySize, G2_SMEM);
        cudaFuncSetAttribute(k_attn,  cudaFuncAttributeMaxDynamicSharedMemorySize, ATTN_SMEM);
        configured = 1;
    }

    k_convX<<<NT * 64 / 256, 256>>>(tokens);
    k_convW<<<1280 * 64 / 256, 256>>>(Wq, Wk, Wv, Wr, Wo);
    k_gemm1<<<dim3(8, 1024), 256, G1_SMEM>>>();
    k_attn<<<NB / 8, 256, ATTN_SMEM>>>(attn);
    k_gemm2<<<NT / 64, 256, G2_SMEM>>>(tokens, ln_g, ln_b, y);
}

// round 5
// speedup vs baseline: 3.6112x; 1.4190x over previous
#include <cuda_runtime.h>
#include <cuda_bf16.h>
#include <math.h>
#include <stdint.h>

#define NB 32768
#define NT (NB*4)              // 131072 tokens
#define QK_SCALE 0.17677669529663687f

// ---------------- scratch (static device globals) ---------------------------
__device__ __align__(16) __nv_bfloat16 g_Xhi[(size_t)NT * 256];  // 67 MB
__device__ __align__(16) __nv_bfloat16 g_Xlo[(size_t)NT * 256];  // 67 MB
__device__ __align__(16) __nv_bfloat16 g_Wqk[(size_t)512 * 768]; // [Q|K] rows, [hi|hi|lo]
__device__ __align__(16) __nv_bfloat16 g_Wvr[(size_t)512 * 256]; // [V|R] rows, hi only
__device__ __align__(16) __nv_bfloat16 g_Wo1[(size_t)256 * 256]; // Wo hi only
__device__ __align__(16) float         g_P[(size_t)NT * 1024];   // QKVR f32, 537 MB
__device__ __align__(16) __nv_bfloat16 g_Ahi[(size_t)NT * 256];  // attn out bf16, 67 MB

// ---------------- PTX helpers ------------------------------------------------
__device__ __forceinline__ uint32_t smem_u32(const void* p) {
    uint32_t a;
    asm("{ .reg .u64 t; cvta.to.shared.u64 t, %1; cvt.u32.u64 %0, t; }" : "=r"(a) : "l"(p));
    return a;
}
__device__ __forceinline__ void cp16(uint32_t dst, const void* src) {
    asm volatile("cp.async.cg.shared.global [%0], [%1], 16;" :: "r"(dst), "l"(src) : "memory");
}
__device__ __forceinline__ void cp_commit() {
    asm volatile("cp.async.commit_group;" ::: "memory");
}
__device__ __forceinline__ void cp_wait1() {
    asm volatile("cp.async.wait_group 1;" ::: "memory");
}
__device__ __forceinline__ void ldm_x4(uint32_t* r, uint32_t addr) {
    asm volatile("ldmatrix.sync.aligned.m8n8.x4.shared.b16 {%0,%1,%2,%3}, [%4];"
                 : "=r"(r[0]), "=r"(r[1]), "=r"(r[2]), "=r"(r[3]) : "r"(addr));
}
__device__ __forceinline__ void mma16816(float* c, const uint32_t* a, uint32_t b0, uint32_t b1) {
    asm volatile(
        "mma.sync.aligned.m16n8k16.row.col.f32.bf16.bf16.f32 "
        "{%0,%1,%2,%3}, {%4,%5,%6,%7}, {%8,%9}, {%0,%1,%2,%3};"
        : "+f"(c[0]), "+f"(c[1]), "+f"(c[2]), "+f"(c[3])
        : "r"(a[0]), "r"(a[1]), "r"(a[2]), "r"(a[3]), "r"(b0), "r"(b1));
}

struct __align__(8) bf4 { __nv_bfloat162 a, b; };
__device__ __forceinline__ bf4 to_bf4(float4 v) {
    bf4 o;
    o.a = __halves2bfloat162(__float2bfloat16(v.x), __float2bfloat16(v.y));
    o.b = __halves2bfloat162(__float2bfloat16(v.z), __float2bfloat16(v.w));
    return o;
}
__device__ __forceinline__ void split4(float4 v, bf4& hi, bf4& lo) {
    __nv_bfloat16 h0 = __float2bfloat16(v.x), h1 = __float2bfloat16(v.y);
    __nv_bfloat16 h2 = __float2bfloat16(v.z), h3 = __float2bfloat16(v.w);
    hi.a = __halves2bfloat162(h0, h1); hi.b = __halves2bfloat162(h2, h3);
    lo.a = __halves2bfloat162(__float2bfloat16(v.x - __bfloat162float(h0)),
                              __float2bfloat16(v.y - __bfloat162float(h1)));
    lo.b = __halves2bfloat162(__float2bfloat16(v.z - __bfloat162float(h2)),
                              __float2bfloat16(v.w - __bfloat162float(h3)));
}

// ============================================================================
// conversions
// ============================================================================
__global__ __launch_bounds__(256) void k_convX(const float* __restrict__ X) {
    long idx = (long)blockIdx.x * 256 + threadIdx.x;   // NT*64 items
    long t = idx >> 6; int col = (int)(idx & 63) * 4;
    float4 v = *(const float4*)(X + t * 256 + col);
    bf4 hi, lo; split4(v, hi, lo);
    *(bf4*)(g_Xhi + t * 256 + col) = hi;
    *(bf4*)(g_Xlo + t * 256 + col) = lo;
}

__global__ __launch_bounds__(256)
void k_convW(const float* __restrict__ Wq, const float* __restrict__ Wk,
             const float* __restrict__ Wv, const float* __restrict__ Wr,
             const float* __restrict__ Wo) {
    long idx = (long)blockIdx.x * 256 + threadIdx.x;   // 1280*64 items
    int j = (int)(idx >> 6); int col = (int)(idx & 63) * 4;
    if (j < 512) {                       // Q,K rows -> [hi|hi|lo]
        const float* src = ((j < 256) ? Wq : Wk) + (size_t)(j & 255) * 256;
        float4 v = *(const float4*)(src + col);
        bf4 hi, lo; split4(v, hi, lo);
        __nv_bfloat16* dst = g_Wqk + (size_t)j * 768;
        *(bf4*)(dst + col)       = hi;
        *(bf4*)(dst + 256 + col) = hi;
        *(bf4*)(dst + 512 + col) = lo;
    } else if (j < 1024) {               // V,R rows -> hi only
        const float* src = ((j < 768) ? Wv : Wr) + (size_t)(j & 255) * 256;
        float4 v = *(const float4*)(src + col);
        *(bf4*)(g_Wvr + (size_t)(j - 512) * 256 + col) = to_bf4(v);
    } else {                             // Wo -> hi only
        float4 v = *(const float4*)(Wo + (size_t)(j - 1024) * 256 + col);
        *(bf4*)(g_Wo1 + (size_t)(j - 1024) * 256 + col) = to_bf4(v);
    }
}

// ---------------- shared tile helpers (64 bf16 = 8x16B chunks per row) -------
__device__ __forceinline__ uint32_t sw_off(int r, int c) {      // bytes
    return (uint32_t)((r * 8 + (c ^ (r & 7))) * 16);
}

// ============================================================================
// GEMM1: g_P[NT,1024] = projections.
// bx<4: QK slab (N 0..511), K=768 compensated [hi|lo|hi] -> 12 chunks
// bx>=4: VR slab (N 512..1023), K=256 single-pass hi -> 4 chunks
// CTA 128x128, 8 warps (32x64 warp tile), 3-stage cp.async, 1 sync/chunk.
// ============================================================================
#define G1_STAGE 32768
#define G1_SMEM  (3 * G1_STAGE)

__global__ void __launch_bounds__(256, 2) k_gemm1() {
    extern __shared__ __align__(1024) char smem[];
    const uint32_t sb = smem_u32(smem);
    const int tid = threadIdx.x;
    const int l = tid & 31, w = tid >> 5;
    const int wm = w & 3, wn = w >> 2;
    const int bx = blockIdx.x;
    const bool qk = (bx < 4);
    const int nch = qk ? 12 : 4;
    const int nloc = (qk ? bx : bx - 4) * 128;       // row within 512-row weight slab
    const int n0 = (qk ? 0 : 512) + nloc;            // global col in g_P
    const size_t row0 = (size_t)blockIdx.y * 128;

    const int lr = tid >> 3, lc = tid & 7;

    float acc[2][8][4];
#pragma unroll
    for (int i = 0; i < 2; i++)
#pragma unroll
        for (int j = 0; j < 8; j++)
#pragma unroll
            for (int k = 0; k < 4; k++) acc[i][j][k] = 0.f;

    auto issue = [&](int s, int buf) {
        const uint32_t sa  = sb + buf * G1_STAGE;
        const uint32_t sbm = sa + 16384;
        const __nv_bfloat16* abase =
            (qk && s >= 4 && s < 8) ? g_Xlo : g_Xhi;
        const int acol = (s & 3) * 64;
#pragma unroll
        for (int u = 0; u < 4; u++) {
            int r = lr + u * 32;
            cp16(sa + sw_off(r, lc), abase + (row0 + r) * 256 + acol + lc * 8);
        }
        if (qk) {
#pragma unroll
            for (int u = 0; u < 4; u++) {
                int r = lr + u * 32;
                cp16(sbm + sw_off(r, lc), g_Wqk + (size_t)(nloc + r) * 768 + s * 64 + lc * 8);
            }
        } else {
#pragma unroll
            for (int u = 0; u < 4; u++) {
                int r = lr + u * 32;
                cp16(sbm + sw_off(r, lc), g_Wvr + (size_t)(nloc + r) * 256 + s * 64 + lc * 8);
            }
        }
    };

    issue(0, 0); cp_commit();
    issue(1, 1); cp_commit();

    int buf = 0;
    for (int s = 0; s < nch; s++) {
        cp_wait1();
        __syncthreads();
        if (s + 2 < nch) { issue(s + 2, (buf + 2) % 3); cp_commit(); }
        else             { cp_commit(); }   // keep group accounting uniform

        const uint32_t sa  = sb + buf * G1_STAGE;
        const uint32_t sbm = sa + 16384;
#pragma unroll
        for (int ks = 0; ks < 4; ks++) {
            uint32_t a[2][4], b[4][4];
            const int cc = ks * 2 + (l >> 4);
#pragma unroll
            for (int mi = 0; mi < 2; mi++) {
                int r = wm * 32 + mi * 16 + (l & 15);
                ldm_x4(a[mi], sa + sw_off(r, cc));
            }
#pragma unroll
            for (int ni = 0; ni < 4; ni++) {
                int r = wn * 64 + ni * 16 + (l & 15);
                ldm_x4(b[ni], sbm + sw_off(r, cc));
            }
#pragma unroll
            for (int mi = 0; mi < 2; mi++)
#pragma unroll
                for (int ni = 0; ni < 4; ni++) {
                    mma16816(acc[mi][ni * 2],     a[mi], b[ni][0], b[ni][2]);
                    mma16816(acc[mi][ni * 2 + 1], a[mi], b[ni][1], b[ni][3]);
                }
        }
        buf = (buf + 1) % 3;
    }

#pragma unroll
    for (int mi = 0; mi < 2; mi++) {
        size_t rbase = row0 + wm * 32 + mi * 16 + (l >> 2);
#pragma unroll
        for (int ni = 0; ni < 8; ni++) {
            int col = n0 + wn * 64 + ni * 8 + (l & 3) * 2;
            *(float2*)(g_P + rbase * 1024 + col) =
                make_float2(acc[mi][ni][0], acc[mi][ni][1]);
            *(float2*)(g_P + (rbase + 8) * 1024 + col) =
                make_float2(acc[mi][ni][2], acc[mi][ni][3]);
        }
    }
}

// ============================================================================
// attention: 8 warps/block, one sample per warp; writes attn + g_Ahi (bf16)
// ============================================================================
#define APAD 36
#define TOKSTRIDE (8 * APAD)
#define WARPSM (2 * 4 * TOKSTRIDE)
#define ATTN_SMEM (8 * WARPSM * 4)     // 73728 B

__global__ void __launch_bounds__(256) k_attn(float* __restrict__ attn_out)
{
    extern __shared__ __align__(16) float sm[];
    const int wid = threadIdx.x >> 5;
    const int lane = threadIdx.x & 31;
    const int b = blockIdx.x * 8 + wid;
    float* sK = sm + wid * WARPSM;
    float* sV = sK + 4 * TOKSTRIDE;
    const size_t rowb = (size_t)b * 4;

    // ---- phase 1: stage K, compute V_eff once per token ----
#pragma unroll
    for (int i = 0; i < 4; i++) {
        const float* base = g_P + (rowb + i) * 1024;
        int o0 = lane * 4, o1 = (32 + lane) * 4;
        float4 k0 = *(const float4*)(base + 256 + o0);
        float4 v0 = *(const float4*)(base + 512 + o0);
        float4 r0 = *(const float4*)(base + 768 + o0);
        float4 k1 = *(const float4*)(base + 256 + o1);
        float4 v1 = *(const float4*)(base + 512 + o1);
        float4 r1 = *(const float4*)(base + 768 + o1);
        int h0 = o0 >> 5, d0 = o0 & 31;
        int h1 = o1 >> 5, d1 = o1 & 31;
        *(float4*)(sK + (i * 8 + h0) * APAD + d0) = k0;
        *(float4*)(sK + (i * 8 + h1) * APAD + d1) = k1;
        float4 ve0, ve1;
        ve0.x = v0.x / (1.f + __expf(-r0.x)); ve0.y = v0.y / (1.f + __expf(-r0.y));
        ve0.z = v0.z / (1.f + __expf(-r0.z)); ve0.w = v0.w / (1.f + __expf(-r0.w));
        ve1.x = v1.x / (1.f + __expf(-r1.x)); ve1.y = v1.y / (1.f + __expf(-r1.y));
        ve1.z = v1.z / (1.f + __expf(-r1.z)); ve1.w = v1.w / (1.f + __expf(-r1.w));
        *(float4*)(sV + (i * 8 + h0) * APAD + d0) = ve0;
        *(float4*)(sV + (i * 8 + h1) * APAD + d1) = ve1;
    }
    __syncwarp();

    // ---- phase 2: per-lane (i,h) attention ----
    const int i = lane >> 3;
    const int h = lane & 7;
    const size_t t = rowb + i;

    float4 Q[8];
    const float* qp = g_P + t * 1024 + h * 32;
#pragma unroll
    for (int c = 0; c < 8; c++) Q[c] = *(const float4*)(qp + c * 4);

    float s[3];
#pragma unroll
    for (int lix = 0; lix < 3; lix++) {
        int nb = (lix >= i) ? lix + 1 : lix;
        const float* kp = sK + (nb * 8 + h) * APAD;
        float a0 = 0.f, a1 = 0.f;
#pragma unroll
        for (int c = 0; c < 4; c++) {
            float4 k0 = *(const float4*)(kp + c * 8);
            float4 k1 = *(const float4*)(kp + c * 8 + 4);
            float4 q0 = Q[c * 2], q1 = Q[c * 2 + 1];
            a0 = fmaf(q0.x, k0.x, a0); a0 = fmaf(q0.y, k0.y, a0);
            a0 = fmaf(q0.z, k0.z, a0); a0 = fmaf(q0.w, k0.w, a0);
            a1 = fmaf(q1.x, k1.x, a1); a1 = fmaf(q1.y, k1.y, a1);
            a1 = fmaf(q1.z, k1.z, a1); a1 = fmaf(q1.w, k1.w, a1);
        }
        s[lix] = (a0 + a1) * QK_SCALE;
    }

    float m = fmaxf(s[0], fmaxf(s[1], s[2]));
    float e0 = __expf(s[0] - m), e1 = __expf(s[1] - m), e2 = __expf(s[2] - m);
    float inv = 1.f / (e0 + e1 + e2);
    float a[3] = { e0 * inv, e1 * inv, e2 * inv };

    size_t ao = (t * 8 + h) * 3;
    attn_out[ao + 0] = a[0]; attn_out[ao + 1] = a[1]; attn_out[ao + 2] = a[2];

    float O[32];
#pragma unroll
    for (int d = 0; d < 32; d++) O[d] = 0.f;
#pragma unroll
    for (int lix = 0; lix < 3; lix++) {
        int nb = (lix >= i) ? lix + 1 : lix;
        const float* vp = sV + (nb * 8 + h) * APAD;
        float al = a[lix];
#pragma unroll
        for (int c = 0; c < 8; c++) {
            float4 v = *(const float4*)(vp + c * 4);
            O[c*4+0] = fmaf(al, v.x, O[c*4+0]);
            O[c*4+1] = fmaf(al, v.y, O[c*4+1]);
            O[c*4+2] = fmaf(al, v.z, O[c*4+2]);
            O[c*4+3] = fmaf(al, v.w, O[c*4+3]);
        }
    }
    __nv_bfloat16* row = g_Ahi + t * 256 + h * 32;
#pragma unroll
    for (int d4 = 0; d4 < 8; d4++)
        *(bf4*)(row + d4 * 4) =
            to_bf4(make_float4(O[d4*4+0], O[d4*4+1], O[d4*4+2], O[d4*4+3]));
}

// ============================================================================
// GEMM2 + residual + LN: y = LN(tok + g_Ahi @ g_Wo1^T), K=256 single-pass
// CTA 64x256, 8 warps (32x64), 2-stage cp.async.
// ============================================================================
#define G2_A0 0
#define G2_B0 16384
#define G2_SMEM 81920

__global__ void __launch_bounds__(256)
k_gemm2(const float* __restrict__ tok, const float* __restrict__ gma,
        const float* __restrict__ bta, float* __restrict__ Y)
{
    extern __shared__ __align__(1024) char smem[];
    const uint32_t sb = smem_u32(smem);
    const int tid = threadIdx.x;
    const int l = tid & 31, w = tid >> 5;
    const int wm = w & 1, wn = w >> 1;
    const size_t row0 = (size_t)blockIdx.x * 64;

    const int lr = tid >> 3, lc = tid & 7;

    float acc[2][8][4];
#pragma unroll
    for (int i = 0; i < 2; i++)
#pragma unroll
        for (int j = 0; j < 8; j++)
#pragma unroll
            for (int k = 0; k < 4; k++) acc[i][j][k] = 0.f;

    auto issue = [&](int s, int buf) {
        const int k0 = s * 64;
        const uint32_t sa = sb + G2_A0 + buf * 8192;
        const uint32_t sbm = sb + G2_B0 + buf * 32768;
#pragma unroll
        for (int u = 0; u < 2; u++) {
            int r = lr + u * 32;
            cp16(sa + sw_off(r, lc), g_Ahi + (row0 + r) * 256 + k0 + lc * 8);
        }
#pragma unroll
        for (int u = 0; u < 8; u++) {
            int r = lr + u * 32;
            cp16(sbm + sw_off(r, lc), g_Wo1 + (size_t)r * 256 + k0 + lc * 8);
        }
    };

    issue(0, 0); cp_commit();

    for (int s = 0; s < 4; s++) {
        if (s + 1 < 4) issue(s + 1, (s + 1) & 1);
        cp_commit();
        cp_wait1();
        __syncthreads();

        const uint32_t sa = sb + G2_A0 + (s & 1) * 8192;
        const uint32_t sbm = sb + G2_B0 + (s & 1) * 32768;
#pragma unroll
        for (int ks = 0; ks < 4; ks++) {
            uint32_t a[2][4], b[4][4];
            const int cc = ks * 2 + (l >> 4);
#pragma unroll
            for (int mi = 0; mi < 2; mi++) {
                int r = wm * 32 + mi * 16 + (l & 15);
                ldm_x4(a[mi], sa + sw_off(r, cc));
            }
#pragma unroll
            for (int ni = 0; ni < 4; ni++) {
                int r = wn * 64 + ni * 16 + (l & 15);
                ldm_x4(b[ni], sbm + sw_off(r, cc));
            }
#pragma unroll
            for (int mi = 0; mi < 2; mi++)
#pragma unroll
                for (int ni = 0; ni < 4; ni++) {
                    mma16816(acc[mi][ni * 2],     a[mi], b[ni][0], b[ni][2]);
                    mma16816(acc[mi][ni * 2 + 1], a[mi], b[ni][1], b[ni][3]);
                }
        }
        __syncthreads();
    }

    float* sred = (float*)smem;
    __syncthreads();
#pragma unroll
    for (int mi = 0; mi < 2; mi++) {
        int rb = wm * 32 + mi * 16 + (l >> 2);
#pragma unroll
        for (int ni = 0; ni < 8; ni++) {
            int col = wn * 64 + ni * 8 + (l & 3) * 2;
            *(float2*)(sred + rb * 260 + col) = make_float2(acc[mi][ni][0], acc[mi][ni][1]);
            *(float2*)(sred + (rb + 8) * 260 + col) = make_float2(acc[mi][ni][2], acc[mi][ni][3]);
        }
    }
    __syncthreads();

#pragma unroll
    for (int rr = 0; rr < 8; rr++) {
        int row = w * 8 + rr;
        size_t grow = row0 + row;
        float v[8];
        float4 t0 = *(const float4*)(tok + grow * 256 + l * 8);
        float4 t1 = *(const float4*)(tok + grow * 256 + l * 8 + 4);
        float4 s0 = *(const float4*)(sred + row * 260 + l * 8);
        float4 s1 = *(const float4*)(sred + row * 260 + l * 8 + 4);
        v[0] = s0.x + t0.x; v[1] = s0.y + t0.y; v[2] = s0.z + t0.z; v[3] = s0.w + t0.w;
        v[4] = s1.x + t1.x; v[5] = s1.y + t1.y; v[6] = s1.z + t1.z; v[7] = s1.w + t1.w;

        float sum = 0.f, sq = 0.f;
#pragma unroll
        for (int u = 0; u < 8; u++) { sum += v[u]; sq += v[u] * v[u]; }
#pragma unroll
        for (int off = 16; off >= 1; off >>= 1) {
            sum += __shfl_xor_sync(0xffffffffu, sum, off);
            sq  += __shfl_xor_sync(0xffffffffu, sq, off);
        }
        float mu = sum * (1.f / 256.f);
        float var = sq * (1.f / 256.f) - mu * mu;
        float is = rsqrtf(var + 1e-5f);

        float4 g0 = *(const float4*)(gma + l * 8);
        float4 g1 = *(const float4*)(gma + l * 8 + 4);
        float4 b0 = *(const float4*)(bta + l * 8);
        float4 b1 = *(const float4*)(bta + l * 8 + 4);
        *(float4*)(Y + grow * 256 + l * 8) = make_float4(
            (v[0]-mu)*is*g0.x + b0.x, (v[1]-mu)*is*g0.y + b0.y,
            (v[2]-mu)*is*g0.z + b0.z, (v[3]-mu)*is*g0.w + b0.w);
        *(float4*)(Y + grow * 256 + l * 8 + 4) = make_float4(
            (v[4]-mu)*is*g1.x + b1.x, (v[5]-mu)*is*g1.y + b1.y,
            (v[6]-mu)*is*g1.z + b1.z, (v[7]-mu)*is*g1.w + b1.w);
    }
}

// ============================================================================
extern "C" void kernel_launch(void* const* d_in, const int* in_sizes, int n_in,
                              void* d_out, int out_size)
{
    const float* tokens = (const float*)d_in[0];
    const float* Wq = (const float*)d_in[1];
    const float* Wk = (const float*)d_in[2];
    const float* Wv = (const float*)d_in[3];
    const float* Wr = (const float*)d_in[4];
    const float* Wo = (const float*)d_in[5];
    const float* ln_g = (const float*)d_in[6];
    const float* ln_b = (const float*)d_in[7];

    float* y = (float*)d_out;
    float* attn = y + (size_t)NT * 256;

    static int configured = 0;
    if (!configured) {
        cudaFuncSetAttribute(k_gemm1, cudaFuncAttributeMaxDynamicSharedMemorySize, G1_SMEM);
        cudaFuncSetAttribute(k_gemm2, cudaFuncAttributeMaxDynamicSharedMemorySize, G2_SMEM);
        cudaFuncSetAttribute(k_attn,  cudaFuncAttributeMaxDynamicSharedMemorySize, ATTN_SMEM);
        configured = 1;
    }

    k_convX<<<NT * 64 / 256, 256>>>(tokens);
    k_convW<<<1280 * 64 / 256, 256>>>(Wq, Wk, Wv, Wr, Wo);
    k_gemm1<<<dim3(8, 1024), 256, G1_SMEM>>>();
    k_attn<<<NB / 8, 256, ATTN_SMEM>>>(attn);
    k_gemm2<<<NT / 64, 256, G2_SMEM>>>(tokens, ln_g, ln_b, y);
}